// round 16
// baseline (speedup 1.0000x reference)
#include <cuda_runtime.h>
#include <cstdint>

#define Hh 192
#define Ww 192

// padded tf32-rounded copy of x: [b*32+n][194 rows][208 cols], col = gx+4, row = gy+1
#define PSTRIDE 208
#define PPLANE  40352   // 194*208
__device__ float g_xt[256 * PPLANE];
__device__ float g_part[1024];
__device__ float g_bias[8 * 32];

// xs site layout: [y(18)][x(18)][n(32)] pad->36 u32/site; half = 18*18*36
#define XSITE 36
#define XROWB 144          // site stride bytes
#define XYB   2592         // y stride bytes = 18*144
#define XHALF 11664        // u32 per half

typedef unsigned long long ull;

__device__ __forceinline__ uint32_t cvt_tf32(float x) {
    uint32_t r; asm("cvt.rna.tf32.f32 %0, %1;" : "=r"(r) : "f"(x)); return r;
}
__device__ __forceinline__ void mma_tf32(float d[4], const uint32_t a[4], const uint32_t b[2]) {
    asm("mma.sync.aligned.m16n8k8.row.col.f32.tf32.tf32.f32 "
        "{%0,%1,%2,%3},{%4,%5,%6,%7},{%8,%9},{%0,%1,%2,%3};"
        : "+f"(d[0]), "+f"(d[1]), "+f"(d[2]), "+f"(d[3])
        : "r"(a[0]), "r"(a[1]), "r"(a[2]), "r"(a[3]), "r"(b[0]), "r"(b[1]));
}
__device__ __forceinline__ void mma_tf32_z(float d[4], const uint32_t a[4], const uint32_t b[2],
                                           const float z[4]) {
    asm("mma.sync.aligned.m16n8k8.row.col.f32.tf32.tf32.f32 "
        "{%0,%1,%2,%3},{%4,%5,%6,%7},{%8,%9},{%10,%11,%12,%13};"
        : "=f"(d[0]), "=f"(d[1]), "=f"(d[2]), "=f"(d[3])
        : "r"(a[0]), "r"(a[1]), "r"(a[2]), "r"(a[3]), "r"(b[0]), "r"(b[1]),
          "f"(z[0]), "f"(z[1]), "f"(z[2]), "f"(z[3]));
}
__device__ __forceinline__ void ldsm4(uint32_t a[4], uint32_t addr) {
    asm volatile("ldmatrix.sync.aligned.m8n8.x4.shared.b16 {%0,%1,%2,%3}, [%4];"
        : "=r"(a[0]), "=r"(a[1]), "=r"(a[2]), "=r"(a[3]) : "r"(addr));
}
__device__ __forceinline__ void barh(int th) {
    asm volatile("bar.sync %0, %1;" :: "r"(th + 1), "r"(256) : "memory");
}

// ---------------------------------------------------------------------------
// Kernel 1: prep — 4 CTAs per plane, 9 batched LDG.128 then cvt+store.
// ---------------------------------------------------------------------------
__global__ __launch_bounds__(256, 8)
void prep_kernel(const float* __restrict__ x) {
    int blk = blockIdx.x;
    int plane = blk >> 2, qt = blk & 3;
    const float4* src = (const float4*)(x + (size_t)plane * (Hh * Ww));
    uint32_t* dst = (uint32_t*)(g_xt + (size_t)plane * PPLANE);
    int t = threadIdx.x;

    float4 v[9];
#pragma unroll
    for (int k = 0; k < 9; k++) v[k] = src[qt * 2304 + t + k * 256];

    float s = 0.f;
#pragma unroll
    for (int k = 0; k < 9; k++) s += (v[k].x + v[k].y) + (v[k].z + v[k].w);

#pragma unroll
    for (int k = 0; k < 9; k++) {
        int i = qt * 2304 + t + k * 256;
        uint4 w;
        w.x = cvt_tf32(v[k].x); w.y = cvt_tf32(v[k].y);
        w.z = cvt_tf32(v[k].z); w.w = cvt_tf32(v[k].w);
        int gy = i / 48, gx4 = i % 48;
        *(uint4*)(dst + (gy + 1) * PSTRIDE + 4 + gx4 * 4) = w;
    }
    if (qt == 0 && t < 52)
        *(uint4*)(dst + t * 4) = make_uint4(0u, 0u, 0u, 0u);
    if (qt == 3 && t < 52)
        *(uint4*)(dst + 193 * PSTRIDE + t * 4) = make_uint4(0u, 0u, 0u, 0u);
    for (int i = t; i < 192; i += 256) {
        int row = 1 + qt * 48 + (i >> 2);
        int c4sel = i & 3;
        int c4 = (c4sel == 0) ? 0 : (48 + c4sel);
        *(uint4*)(dst + row * PSTRIDE + c4 * 4) = make_uint4(0u, 0u, 0u, 0u);
    }

#pragma unroll
    for (int o = 16; o > 0; o >>= 1) s += __shfl_xor_sync(0xffffffffu, s, o);
    __shared__ float red[8];
    if ((t & 31) == 0) red[t >> 5] = s;
    __syncthreads();
    if (t == 0) {
        float r = 0.f;
#pragma unroll
        for (int i = 0; i < 8; i++) r += red[i];
        g_part[blk] = r;
    }
}

// ---------------------------------------------------------------------------
// Kernel 2: bias MLP.
// ---------------------------------------------------------------------------
__global__ void bias_kernel(const float* __restrict__ b1w, const float* __restrict__ b1b,
                            const float* __restrict__ b2w, const float* __restrict__ b2b) {
    __shared__ float ps[256];
    __shared__ float h[8 * 32];
    int t = threadIdx.x;
    ps[t] = (g_part[4 * t] + g_part[4 * t + 1] + g_part[4 * t + 2] + g_part[4 * t + 3])
            * (1.f / (Hh * Ww));
    __syncthreads();
    int b = t >> 5, k = t & 31;
    float s = b1b[k];
    for (int n = 0; n < 32; n++) s += ps[b * 32 + n] * b1w[k * 32 + n];
    h[t] = fmaxf(s, 0.f);
    __syncthreads();
    int m = k;
    float s2 = b2b[m];
    for (int kk = 0; kk < 32; kk++) s2 += h[b * 32 + kk] * b2w[m * 32 + kk];
    g_bias[t] = s2;
}

// ---------------------------------------------------------------------------
// Fused kernel: xs in [y][x][n] site layout; A fragments via ldmatrix.x4.b16
// (one LDSM per fragment). B in ull-pair layout (one LDS.64). G-merge main
// loop with exact fp32 attention. Per-half phases via named barriers.
// ---------------------------------------------------------------------------
__global__ __launch_bounds__(512, 1)
void fused_kernel(const float* __restrict__ a1w, const float* __restrict__ a1b,
                  const float* __restrict__ a2w, const float* __restrict__ a2b,
                  const float* __restrict__ a3w, const float* __restrict__ a3b,
                  const float* __restrict__ weight, float* __restrict__ out) {
    extern __shared__ uint32_t smu[];
    uint32_t* xs = smu;                     // 2 * XHALF = 23328
    uint32_t* w1t2 = smu + 23328;           // 5760
    uint32_t* ws2 = smu + 29088;            // 11520
    uint32_t* trbase = smu + 40608;         // 2 * 4608
    float* sbias = (float*)(smu + 49824);   // 64
    float* w2 = sbias + 64;                 // 81
    float* w3 = w2 + 81;                    // 81
    float* bb1 = w3 + 81;                   // 9
    float* bb2 = bb1 + 9;                   // 9
    float* bb3 = bb2 + 9;                   // 9

    int tid = threadIdx.x;
    uint32_t xs_sh = (uint32_t)__cvta_generic_to_shared(xs);

    for (int i = tid; i < 5760; i += 512) {
        int t = i / 640;
        int r = i % 640;
        int o = r / 40, c = r % 40;
        int pair = c >> 1, e = c & 1;
        uint32_t v = 0u;
        if (o < 9 && pair < 16) {
            int n = 8 * (pair >> 2) + (pair & 3) + 4 * e;
            v = cvt_tf32(a1w[o * 288 + n * 9 + t]);
        }
        w1t2[i] = v;
    }
    for (int i = tid; i < 11520; i += 512) {
        int p = i / 1280;
        int r = i % 1280;
        int m = r / 40, c = r % 40;
        int pair = c >> 1, e = c & 1;
        uint32_t v = 0u;
        if (pair < 16) {
            int n = 8 * (pair >> 2) + (pair & 3) + 4 * e;
            v = cvt_tf32(weight[(m * 32 + n) * 9 + p]);
        }
        ws2[i] = v;
    }
    if (tid < 81) { w2[tid] = a2w[tid]; w3[tid] = a3w[tid]; }
    if (tid < 9) { bb1[tid] = a1b[tid]; bb2[tid] = a2b[tid]; bb3[tid] = a3b[tid]; }
    __syncthreads();

    int wid = tid >> 5, lane = tid & 31;
    int r4 = lane >> 2, k0 = lane & 3;
    int th = wid >> 3;
    int tloc = tid & 255;
    int yA = 2 * (wid & 7);

    const ull* w1u = (const ull*)w1t2;
    const ull* wsu = (const ull*)ws2;

    // per-lane ldmatrix offset: row = x (l&15), col-block (l>>4)*16B
    uint32_t lm_base = xs_sh + th * (XHALF * 4) + (lane & 15) * XROWB + (lane >> 4) * 16;

    const float zq[4] = {0.f, 0.f, 0.f, 0.f};

    for (int it = 0; it < 4; it++) {
        int pairIdx = blockIdx.x * 4 + it;
        int b = pairIdx / 72;
        int rr = pairIdx % 72;
        int y0 = (rr / 6) * 16;
        int x0 = (rr % 6) * 32 + th * 16;

        barh(th);

        // xs fill: per (n,y) row, 6 coalesced LDG.128 then 18 STS.32 to sites
        for (int r = tloc; r < 576; r += 256) {
            int n = r / 18, y = r - n * 18;
            const float4* src = (const float4*)(g_xt + (size_t)(b * 32 + n) * PPLANE
                                                + (y0 + y) * PSTRIDE + x0);
            float4 v[6];
#pragma unroll
            for (int j4 = 0; j4 < 6; j4++) v[j4] = src[j4];
            const float* vf = (const float*)v;
            uint32_t* site = xs + th * XHALF + (y * 18) * XSITE + n;
#pragma unroll
            for (int j = 3; j <= 20; j++)
                site[(j - 3) * XSITE] = __float_as_uint(vf[j]);
        }
        if (tloc < 32) sbias[th * 32 + tloc] = g_bias[b * 32 + tloc];
        barh(th);

        // ---- attention mainloop: LDSM -> MMA ----
        float DA[2][2][4];
#pragma unroll
        for (int f = 0; f < 2; f++)
#pragma unroll
            for (int oc = 0; oc < 2; oc++)
#pragma unroll
                for (int e = 0; e < 4; e++) DA[f][oc][e] = 0.f;

#pragma unroll
        for (int t = 0; t < 9; t++) {
            const int ki = t / 3, kj = t % 3;
            const ull* wbT = w1u + t * 320 + r4 * 20 + k0;
            uint32_t abase = lm_base + ((yA + ki) * 18 + kj) * XROWB;
#pragma unroll
            for (int q = 0; q < 4; q++) {
                uint32_t a0[4], a1[4];
                ldsm4(a0, abase + 32 * q);
                ldsm4(a1, abase + XYB + 32 * q);
#pragma unroll
                for (int oc = 0; oc < 2; oc++) {
                    ull wv = wbT[oc * 160 + 4 * q];
                    uint32_t bb[2] = {(uint32_t)wv, (uint32_t)(wv >> 32)};
                    mma_tf32(DA[0][oc], a0, bb);
                    mma_tf32(DA[1][oc], a1, bb);
                }
            }
        }

        // transpose DA -> tr
        {
            ull* tr = (ull*)(trbase + th * 4608);
#pragma unroll
            for (int f = 0; f < 2; f++) {
                int yy = yA + f;
#pragma unroll
                for (int oc = 0; oc < 2; oc++) {
                    int pr = oc * 4 + k0;
                    float2 lo2 = make_float2(DA[f][oc][0], DA[f][oc][1]);
                    float2 hi2 = make_float2(DA[f][oc][2], DA[f][oc][3]);
                    tr[(yy * 16 + r4) * 9 + pr]     = *(ull*)&lo2;
                    tr[(yy * 16 + r4 + 8) * 9 + pr] = *(ull*)&hi2;
                }
            }
        }
        barh(th);

        // attention epilogue; atts overlays tr, layout [px][13]
        {
            int px = tloc;
            const ull* trt = (const ull*)(trbase + th * 4608);
            float u[10], z[9], att[9];
#pragma unroll
            for (int j = 0; j < 5; j++) {
                float2 v = *(float2*)&trt[px * 9 + j];
                u[2 * j] = v.x;
                u[2 * j + 1] = v.y;
            }
#pragma unroll
            for (int o = 0; o < 9; o++) u[o] = fmaxf(u[o] + bb1[o], 0.f);
#pragma unroll
            for (int o2 = 0; o2 < 9; o2++) {
                float s = bb2[o2];
#pragma unroll
                for (int o = 0; o < 9; o++) s += w2[o2 * 9 + o] * u[o];
                z[o2] = fmaxf(s, 0.f);
            }
#pragma unroll
            for (int o3 = 0; o3 < 9; o3++) {
                float s = bb3[o3];
#pragma unroll
                for (int o2 = 0; o2 < 9; o2++) s += w3[o3 * 9 + o2] * z[o2];
                att[o3] = 1.f / (1.f + __expf(-s));
            }
            barh(th);
            float* atts_t = (float*)(trbase + th * 4608);
#pragma unroll
            for (int o3 = 0; o3 < 9; o3++) atts_t[px * 13 + o3] = att[o3];
        }
        barh(th);

        // ---- main mainloop: LDSM -> MMA into G, exact fp32 att merge ----
        const float* atts = (const float*)(trbase + th * 4608);
        float D[2][4][4];
#pragma unroll
        for (int f = 0; f < 2; f++)
#pragma unroll
            for (int mc = 0; mc < 4; mc++)
#pragma unroll
                for (int e = 0; e < 4; e++) D[f][mc][e] = 0.f;

#pragma unroll
        for (int p = 0; p < 9; p++) {
            const int ki = p / 3, kj = p % 3;
            float G[2][4][4];
            const ull* wbP = wsu + p * 640 + r4 * 20 + k0;
            uint32_t abase = lm_base + ((yA + ki) * 18 + kj) * XROWB;
            {
                uint32_t a0[4], a1[4];
                ldsm4(a0, abase);
                ldsm4(a1, abase + XYB);
#pragma unroll
                for (int mc = 0; mc < 4; mc++) {
                    ull wv = wbP[mc * 160];
                    uint32_t bb[2] = {(uint32_t)wv, (uint32_t)(wv >> 32)};
                    mma_tf32_z(G[0][mc], a0, bb, zq);
                    mma_tf32_z(G[1][mc], a1, bb, zq);
                }
            }
#pragma unroll
            for (int q = 1; q < 4; q++) {
                uint32_t a0[4], a1[4];
                ldsm4(a0, abase + 32 * q);
                ldsm4(a1, abase + XYB + 32 * q);
#pragma unroll
                for (int mc = 0; mc < 4; mc++) {
                    ull wv = wbP[mc * 160 + 4 * q];
                    uint32_t bb[2] = {(uint32_t)wv, (uint32_t)(wv >> 32)};
                    mma_tf32(G[0][mc], a0, bb);
                    mma_tf32(G[1][mc], a1, bb);
                }
            }
            float attA0 = atts[(yA * 16 + r4) * 13 + p];
            float attB0 = atts[(yA * 16 + r4 + 8) * 13 + p];
            float attA1 = atts[((yA + 1) * 16 + r4) * 13 + p];
            float attB1 = atts[((yA + 1) * 16 + r4 + 8) * 13 + p];
#pragma unroll
            for (int mc = 0; mc < 4; mc++) {
                D[0][mc][0] += attA0 * G[0][mc][0];
                D[0][mc][1] += attA0 * G[0][mc][1];
                D[0][mc][2] += attB0 * G[0][mc][2];
                D[0][mc][3] += attB0 * G[0][mc][3];
                D[1][mc][0] += attA1 * G[1][mc][0];
                D[1][mc][1] += attA1 * G[1][mc][1];
                D[1][mc][2] += attB1 * G[1][mc][2];
                D[1][mc][3] += attB1 * G[1][mc][3];
            }
        }

        // store
        {
#pragma unroll
            for (int f = 0; f < 2; f++) {
                int gy = y0 + yA + f;
#pragma unroll
                for (int mc = 0; mc < 4; mc++) {
                    int m = mc * 8 + 2 * k0;
                    float bv0 = sbias[th * 32 + m], bv1 = sbias[th * 32 + m + 1];
                    float* o0 = out + ((size_t)(b * 32 + m) * Hh + gy) * Ww + x0;
                    float* o1 = o0 + (size_t)Hh * Ww;
                    o0[r4]     = D[f][mc][0] + bv0;
                    o1[r4]     = D[f][mc][1] + bv1;
                    o0[r4 + 8] = D[f][mc][2] + bv0;
                    o1[r4 + 8] = D[f][mc][3] + bv1;
                }
            }
        }
    }
}

// ---------------------------------------------------------------------------
extern "C" void kernel_launch(void* const* d_in, const int* in_sizes, int n_in,
                              void* d_out, int out_size) {
    const float* x   = (const float*)d_in[0];
    const float* a1w = (const float*)d_in[1];
    const float* a1b = (const float*)d_in[2];
    const float* a2w = (const float*)d_in[3];
    const float* a2b = (const float*)d_in[4];
    const float* a3w = (const float*)d_in[5];
    const float* a3b = (const float*)d_in[6];
    const float* b1w = (const float*)d_in[7];
    const float* b1b = (const float*)d_in[8];
    const float* b2w = (const float*)d_in[9];
    const float* b2b = (const float*)d_in[10];
    const float* wgt = (const float*)d_in[11];
    float* out = (float*)d_out;

    prep_kernel<<<1024, 256>>>(x);
    bias_kernel<<<1, 256>>>(b1w, b1b, b2w, b2b);

    int smF = (49824 + 64 + 81 + 81 + 9 + 9 + 9 + 3) * (int)sizeof(uint32_t);
    cudaFuncSetAttribute(fused_kernel, cudaFuncAttributeMaxDynamicSharedMemorySize, smF);
    fused_kernel<<<144, 512, smF>>>(a1w, a1b, a2w, a2b, a3w, a3b, wgt, out);
}